// round 1
// baseline (speedup 1.0000x reference)
#include <cuda_runtime.h>

// ---------------- DCT-II 8-point constants (fp32, match np.float32(D)) ----
#define G_ 0.35355339059327373f
#define A_ 0.49039264020161522f
#define B_ 0.41573480615127262f
#define C_ 0.27778511650980114f
#define D_ 0.09754516100806417f
#define E_ 0.46193976625564337f
#define F_ 0.19134171618254492f

// Quant tables for QUALITY=95: q = floor((base+5)/10), clipped to [1,255].
// Stored TRANSPOSED (thread k holds column k of coef), luma not symmetric.
__constant__ float c_qlt[64] = {
    2,1,1,1,2,2,5,7,
    1,1,1,2,2,4,6,9,
    1,1,2,2,4,6,8,10,
    2,2,2,3,6,6,9,10,
    2,3,4,5,7,8,10,11,
    4,6,6,9,11,10,12,10,
    5,6,7,8,10,11,12,10,
    6,6,6,6,8,9,10,10
};
__constant__ float c_iqlt[64] = {
    1.0f/2,1.0f/1,1.0f/1,1.0f/1,1.0f/2,1.0f/2,1.0f/5,1.0f/7,
    1.0f/1,1.0f/1,1.0f/1,1.0f/2,1.0f/2,1.0f/4,1.0f/6,1.0f/9,
    1.0f/1,1.0f/1,1.0f/2,1.0f/2,1.0f/4,1.0f/6,1.0f/8,1.0f/10,
    1.0f/2,1.0f/2,1.0f/2,1.0f/3,1.0f/6,1.0f/6,1.0f/9,1.0f/10,
    1.0f/2,1.0f/3,1.0f/4,1.0f/5,1.0f/7,1.0f/8,1.0f/10,1.0f/11,
    1.0f/4,1.0f/6,1.0f/6,1.0f/9,1.0f/11,1.0f/10,1.0f/12,1.0f/10,
    1.0f/5,1.0f/6,1.0f/7,1.0f/8,1.0f/10,1.0f/11,1.0f/12,1.0f/10,
    1.0f/6,1.0f/6,1.0f/6,1.0f/6,1.0f/8,1.0f/9,1.0f/10,1.0f/10
};
// chroma table is symmetric -> transpose == itself
__constant__ float c_qct[64] = {
    2,2,2,5,10,10,10,10,
    2,2,3,7,10,10,10,10,
    2,3,6,10,10,10,10,10,
    5,7,10,10,10,10,10,10,
    10,10,10,10,10,10,10,10,
    10,10,10,10,10,10,10,10,
    10,10,10,10,10,10,10,10,
    10,10,10,10,10,10,10,10
};
__constant__ float c_iqct[64] = {
    1.0f/2,1.0f/2,1.0f/2,1.0f/5,1.0f/10,1.0f/10,1.0f/10,1.0f/10,
    1.0f/2,1.0f/2,1.0f/3,1.0f/7,1.0f/10,1.0f/10,1.0f/10,1.0f/10,
    1.0f/2,1.0f/3,1.0f/6,1.0f/10,1.0f/10,1.0f/10,1.0f/10,1.0f/10,
    1.0f/5,1.0f/7,1.0f/10,1.0f/10,1.0f/10,1.0f/10,1.0f/10,1.0f/10,
    1.0f/10,1.0f/10,1.0f/10,1.0f/10,1.0f/10,1.0f/10,1.0f/10,1.0f/10,
    1.0f/10,1.0f/10,1.0f/10,1.0f/10,1.0f/10,1.0f/10,1.0f/10,1.0f/10,
    1.0f/10,1.0f/10,1.0f/10,1.0f/10,1.0f/10,1.0f/10,1.0f/10,1.0f/10,
    1.0f/10,1.0f/10,1.0f/10,1.0f/10,1.0f/10,1.0f/10,1.0f/10,1.0f/10
};

#define IMGW 512
#define TILE 64
#define SYS  68   // padded stride of Y plane in smem
#define SCS  36   // padded stride of chroma planes

// round-to-nearest-even via magic constant (|x| < 2^22 guaranteed here)
__device__ __forceinline__ float rne(float v) {
    float t = fmaf(v, 1.0f, 12582912.0f);   // 1.5 * 2^23
    return fmaf(t, 1.0f, -12582912.0f);
}

// o[l] = sum_j x[j] * D[l][j]   (forward DCT of an 8-vector), butterflied
__device__ __forceinline__ void fdct8(const float x[8], float o[8]) {
    float s07 = x[0] + x[7], s16 = x[1] + x[6], s25 = x[2] + x[5], s34 = x[3] + x[4];
    float d07 = x[0] - x[7], d16 = x[1] - x[6], d25 = x[2] - x[5], d34 = x[3] - x[4];
    float e0 = s07 + s34, e1 = s16 + s25, e2 = s07 - s34, e3 = s16 - s25;
    o[0] = G_ * (e0 + e1);
    o[4] = G_ * (e0 - e1);
    o[2] = fmaf( F_, e3, E_ * e2);
    o[6] = fmaf(-E_, e3, F_ * e2);
    o[1] = fmaf( D_, d34, fmaf( C_, d25, fmaf( B_, d16, A_ * d07)));
    o[3] = fmaf(-C_, d34, fmaf(-A_, d25, fmaf(-D_, d16, B_ * d07)));
    o[5] = fmaf( B_, d34, fmaf( D_, d25, fmaf(-A_, d16, C_ * d07)));
    o[7] = fmaf(-A_, d34, fmaf( B_, d25, fmaf(-C_, d16, D_ * d07)));
}

// o[j] = sum_l x[l] * D[l][j]   (inverse DCT of an 8-vector), butterflied
__device__ __forceinline__ void idct8(const float x[8], float o[8]) {
    float ee0 = G_ * (x[0] + x[4]);
    float ee1 = G_ * (x[0] - x[4]);
    float eo0 = fmaf( F_, x[6], E_ * x[2]);
    float eo1 = fmaf(-E_, x[6], F_ * x[2]);
    float ev0 = ee0 + eo0, ev1 = ee1 + eo1, ev2 = ee1 - eo1, ev3 = ee0 - eo0;
    float od0 = fmaf( D_, x[7], fmaf( C_, x[5], fmaf( B_, x[3], A_ * x[1])));
    float od1 = fmaf(-C_, x[7], fmaf(-A_, x[5], fmaf(-D_, x[3], B_ * x[1])));
    float od2 = fmaf( B_, x[7], fmaf( D_, x[5], fmaf(-A_, x[3], C_ * x[1])));
    float od3 = fmaf(-A_, x[7], fmaf( B_, x[5], fmaf(-C_, x[3], D_ * x[1])));
    o[0] = ev0 + od0; o[1] = ev1 + od1; o[2] = ev2 + od2; o[3] = ev3 + od3;
    o[4] = ev3 - od3; o[5] = ev2 - od2; o[6] = ev1 - od1; o[7] = ev0 - od0;
}

template <int S>
__device__ __forceinline__ void storerow(float* blk, int k, const float a[8]) {
    *reinterpret_cast<float4*>(blk + k * S)     = make_float4(a[0], a[1], a[2], a[3]);
    *reinterpret_cast<float4*>(blk + k * S + 4) = make_float4(a[4], a[5], a[6], a[7]);
}
template <int S>
__device__ __forceinline__ void loadrow(const float* blk, int k, float a[8]) {
    float4 v0 = *reinterpret_cast<const float4*>(blk + k * S);
    float4 v1 = *reinterpret_cast<const float4*>(blk + k * S + 4);
    a[0] = v0.x; a[1] = v0.y; a[2] = v0.z; a[3] = v0.w;
    a[4] = v1.x; a[5] = v1.y; a[6] = v1.z; a[7] = v1.w;
}
template <int S>
__device__ __forceinline__ void loadcol(const float* blk, int k, float a[8]) {
#pragma unroll
    for (int j = 0; j < 8; j++) a[j] = blk[j * S + k];
}

// Full DCT -> quant(RNE) -> dequant -> IDCT of one 8x8 block, done in-place in
// shared memory by an 8-thread group (thread k owns row k). Uses two in-place
// transposes so every matrix multiplier is a compile-time immediate.
template <int S>
__device__ __forceinline__ void jpeg_block(float* blk, int k,
                                           const float q[8], const float iq[8]) {
    float x[8], a[8];
    loadrow<S>(blk, k, x);          // row k of X
    fdct8(x, a);                    // row k of A = X * D^T
    __syncwarp();
    storerow<S>(blk, k, a);         // smem holds A
    __syncwarp();
    loadcol<S>(blk, k, x);          // row k of A^T
    fdct8(x, a);                    // row k of C^T   (C = D X D^T)
#pragma unroll
    for (int l = 0; l < 8; l++)     // quantize + dequantize (table transposed)
        a[l] = rne(a[l] * iq[l]) * q[l];
    idct8(a, x);                    // row k of P^T   (P = D^T * deq)
    __syncwarp();
    storerow<S>(blk, k, x);         // smem holds P^T
    __syncwarp();
    loadcol<S>(blk, k, a);          // row k of P
    idct8(a, x);                    // row k of rec = D^T * deq * D
    __syncwarp();
    storerow<S>(blk, k, x);
}

__global__ void __launch_bounds__(256)
jpeg_kernel(const float* __restrict__ in, float* __restrict__ out) {
    __shared__ float sY[TILE * SYS];
    __shared__ float sCb[32 * SCS];
    __shared__ float sCr[32 * SCS];

    const int tid = threadIdx.x;
    const int tx0 = blockIdx.x * TILE;
    const int ty0 = blockIdx.y * TILE;
    const int img = blockIdx.z;

    const float* src = in  + (((size_t)img * IMGW + ty0) * IMGW + tx0) * 3;
    float*       dst = out + (((size_t)img * IMGW + ty0) * IMGW + tx0) * 3;

    // ---------- phase 1: load, x255, RGB->YCbCr (level shifted), 4:2:0 down ----
#pragma unroll
    for (int qq = 0; qq < 4; qq++) {
        int qid = tid + qq * 256;
        int qr = qid >> 5, qc = qid & 31;
        const float* p = src + (qr * 2) * (IMGW * 3) + qc * 6;
        float cbs = 0.0f, crs = 0.0f;
#pragma unroll
        for (int dy = 0; dy < 2; dy++) {
            const float* pr = p + dy * (IMGW * 3);
            float2 u0 = *reinterpret_cast<const float2*>(pr);
            float2 u1 = *reinterpret_cast<const float2*>(pr + 2);
            float2 u2 = *reinterpret_cast<const float2*>(pr + 4);
            float rv[2] = { u0.x, u1.y };
            float gv[2] = { u0.y, u2.x };
            float bv[2] = { u1.x, u2.y };
#pragma unroll
            for (int dx = 0; dx < 2; dx++) {
                float r = fminf(floorf(rv[dx] * 255.0f), 255.0f);
                float g = fminf(floorf(gv[dx] * 255.0f), 255.0f);
                float b = fminf(floorf(bv[dx] * 255.0f), 255.0f);
                float yv = fmaf(r, 0.299f, fmaf(g, 0.587f, fmaf(b, 0.114f, -128.0f)));
                cbs += fmaf(r, -0.168736f, fmaf(g, -0.331264f, b * 0.5f));
                crs += fmaf(r, 0.5f, fmaf(g, -0.418688f, b * (-0.081312f)));
                sY[(qr * 2 + dy) * SYS + qc * 2 + dx] = yv;
            }
        }
        sCb[qr * SCS + qc] = cbs * 0.25f;
        sCr[qr * SCS + qc] = crs * 0.25f;
    }
    __syncthreads();

    // ---------- phase 2: 8x8 blocks. 32 groups x 3 blocks (2 luma + 1 chroma) --
    {
        const int grp = tid >> 3;
        const int k   = tid & 7;

        float ql[8], iql[8];
#pragma unroll
        for (int l = 0; l < 8; l++) { ql[l] = c_qlt[k * 8 + l]; iql[l] = c_iqlt[k * 8 + l]; }

        float* yb0 = sY + (grp >> 3) * (8 * SYS) + (grp & 7) * 8;
        jpeg_block<SYS>(yb0, k, ql, iql);
        float* yb1 = sY + ((grp >> 3) + 4) * (8 * SYS) + (grp & 7) * 8;
        jpeg_block<SYS>(yb1, k, ql, iql);

        float qc8[8], iqc8[8];
#pragma unroll
        for (int l = 0; l < 8; l++) { qc8[l] = c_qct[k * 8 + l]; iqc8[l] = c_iqct[k * 8 + l]; }

        int cg = grp & 15;
        float* cbase = (grp < 16) ? sCb : sCr;
        float* cb = cbase + (cg >> 2) * (8 * SCS) + (cg & 3) * 8;
        jpeg_block<SCS>(cb, k, qc8, iqc8);
    }
    __syncthreads();

    // ---------- phase 3: upsample chroma, YCbCr->RGB, clip, round, /255 -------
#pragma unroll
    for (int qq = 0; qq < 4; qq++) {
        int qid = tid + qq * 256;
        int qr = qid >> 5, qc = qid & 31;
        float cbv = sCb[qr * SCS + qc];
        float crv = sCr[qr * SCS + qc];
        float* p = dst + (qr * 2) * (IMGW * 3) + qc * 6;
#pragma unroll
        for (int dy = 0; dy < 2; dy++) {
            float* pr = p + dy * (IMGW * 3);
            float vals[6];
#pragma unroll
            for (int dx = 0; dx < 2; dx++) {
                float y128 = sY[(qr * 2 + dy) * SYS + qc * 2 + dx] + 128.0f;
                float r2 = fmaf(crv, 1.402f, y128);
                float g2 = fmaf(cbv, -0.344136f, fmaf(crv, -0.714136f, y128));
                float b2 = fmaf(cbv, 1.772f, y128);
                r2 = rne(fminf(fmaxf(r2, 0.0f), 255.0f)) * (1.0f / 255.0f);
                g2 = rne(fminf(fmaxf(g2, 0.0f), 255.0f)) * (1.0f / 255.0f);
                b2 = rne(fminf(fmaxf(b2, 0.0f), 255.0f)) * (1.0f / 255.0f);
                vals[dx * 3 + 0] = r2; vals[dx * 3 + 1] = g2; vals[dx * 3 + 2] = b2;
            }
            *reinterpret_cast<float2*>(pr)     = make_float2(vals[0], vals[1]);
            *reinterpret_cast<float2*>(pr + 2) = make_float2(vals[2], vals[3]);
            *reinterpret_cast<float2*>(pr + 4) = make_float2(vals[4], vals[5]);
        }
    }
}

extern "C" void kernel_launch(void* const* d_in, const int* in_sizes, int n_in,
                              void* d_out, int out_size) {
    (void)in_sizes; (void)n_in; (void)out_size;
    dim3 grid(IMGW / TILE, IMGW / TILE, 32);
    jpeg_kernel<<<grid, 256>>>((const float*)d_in[0], (float*)d_out);
}

// round 2
// speedup vs baseline: 1.0464x; 1.0464x over previous
#include <cuda_runtime.h>

// ---------------- DCT-II 8-point constants (fp32, match np.float32(D)) ----
#define G_ 0.35355339059327373f
#define A_ 0.49039264020161522f
#define B_ 0.41573480615127262f
#define C_ 0.27778511650980114f
#define D_ 0.09754516100806417f
#define E_ 0.46193976625564337f
#define F_ 0.19134171618254492f

// Quant tables for QUALITY=95: q = floor((base+5)/10), clipped to [1,255].
// Stored TRANSPOSED (thread k holds column k of coef).
// Layout: [0:64) qlt, [64:128) 1/qlt, [128:192) qct, [192:256) 1/qct.
__constant__ float c_tab[256] = {
    // qlt (transposed luma)
    2,1,1,1,2,2,5,7,
    1,1,1,2,2,4,6,9,
    1,1,2,2,4,6,8,10,
    2,2,2,3,6,6,9,10,
    2,3,4,5,7,8,10,11,
    4,6,6,9,11,10,12,10,
    5,6,7,8,10,11,12,10,
    6,6,6,6,8,9,10,10,
    // 1/qlt
    1.0f/2,1.0f/1,1.0f/1,1.0f/1,1.0f/2,1.0f/2,1.0f/5,1.0f/7,
    1.0f/1,1.0f/1,1.0f/1,1.0f/2,1.0f/2,1.0f/4,1.0f/6,1.0f/9,
    1.0f/1,1.0f/1,1.0f/2,1.0f/2,1.0f/4,1.0f/6,1.0f/8,1.0f/10,
    1.0f/2,1.0f/2,1.0f/2,1.0f/3,1.0f/6,1.0f/6,1.0f/9,1.0f/10,
    1.0f/2,1.0f/3,1.0f/4,1.0f/5,1.0f/7,1.0f/8,1.0f/10,1.0f/11,
    1.0f/4,1.0f/6,1.0f/6,1.0f/9,1.0f/11,1.0f/10,1.0f/12,1.0f/10,
    1.0f/5,1.0f/6,1.0f/7,1.0f/8,1.0f/10,1.0f/11,1.0f/12,1.0f/10,
    1.0f/6,1.0f/6,1.0f/6,1.0f/6,1.0f/8,1.0f/9,1.0f/10,1.0f/10,
    // qct (chroma, symmetric)
    2,2,2,5,10,10,10,10,
    2,2,3,7,10,10,10,10,
    2,3,6,10,10,10,10,10,
    5,7,10,10,10,10,10,10,
    10,10,10,10,10,10,10,10,
    10,10,10,10,10,10,10,10,
    10,10,10,10,10,10,10,10,
    10,10,10,10,10,10,10,10,
    // 1/qct
    1.0f/2,1.0f/2,1.0f/2,1.0f/5,1.0f/10,1.0f/10,1.0f/10,1.0f/10,
    1.0f/2,1.0f/2,1.0f/3,1.0f/7,1.0f/10,1.0f/10,1.0f/10,1.0f/10,
    1.0f/2,1.0f/3,1.0f/6,1.0f/10,1.0f/10,1.0f/10,1.0f/10,1.0f/10,
    1.0f/5,1.0f/7,1.0f/10,1.0f/10,1.0f/10,1.0f/10,1.0f/10,1.0f/10,
    1.0f/10,1.0f/10,1.0f/10,1.0f/10,1.0f/10,1.0f/10,1.0f/10,1.0f/10,
    1.0f/10,1.0f/10,1.0f/10,1.0f/10,1.0f/10,1.0f/10,1.0f/10,1.0f/10,
    1.0f/10,1.0f/10,1.0f/10,1.0f/10,1.0f/10,1.0f/10,1.0f/10,1.0f/10,
    1.0f/10,1.0f/10,1.0f/10,1.0f/10,1.0f/10,1.0f/10,1.0f/10,1.0f/10
};

#define IMGW 512
#define TILE 64
#define SYS  68   // padded stride of Y plane in smem
#define SCS  36   // padded stride of chroma planes

// round-to-nearest-even via magic constant (|x| < 2^22 guaranteed here)
__device__ __forceinline__ float rne(float v) {
    float t = fmaf(v, 1.0f, 12582912.0f);   // 1.5 * 2^23
    return fmaf(t, 1.0f, -12582912.0f);
}

// o[l] = sum_j x[j] * D[l][j]   (forward DCT of an 8-vector), butterflied
__device__ __forceinline__ void fdct8(const float x[8], float o[8]) {
    float s07 = x[0] + x[7], s16 = x[1] + x[6], s25 = x[2] + x[5], s34 = x[3] + x[4];
    float d07 = x[0] - x[7], d16 = x[1] - x[6], d25 = x[2] - x[5], d34 = x[3] - x[4];
    float e0 = s07 + s34, e1 = s16 + s25, e2 = s07 - s34, e3 = s16 - s25;
    o[0] = G_ * (e0 + e1);
    o[4] = G_ * (e0 - e1);
    o[2] = fmaf( F_, e3, E_ * e2);
    o[6] = fmaf(-E_, e3, F_ * e2);
    o[1] = fmaf( D_, d34, fmaf( C_, d25, fmaf( B_, d16, A_ * d07)));
    o[3] = fmaf(-C_, d34, fmaf(-A_, d25, fmaf(-D_, d16, B_ * d07)));
    o[5] = fmaf( B_, d34, fmaf( D_, d25, fmaf(-A_, d16, C_ * d07)));
    o[7] = fmaf(-A_, d34, fmaf( B_, d25, fmaf(-C_, d16, D_ * d07)));
}

// o[j] = sum_l x[l] * D[l][j]   (inverse DCT of an 8-vector), butterflied
__device__ __forceinline__ void idct8(const float x[8], float o[8]) {
    float ee0 = G_ * (x[0] + x[4]);
    float ee1 = G_ * (x[0] - x[4]);
    float eo0 = fmaf( F_, x[6], E_ * x[2]);
    float eo1 = fmaf(-E_, x[6], F_ * x[2]);
    float ev0 = ee0 + eo0, ev1 = ee1 + eo1, ev2 = ee1 - eo1, ev3 = ee0 - eo0;
    float od0 = fmaf( D_, x[7], fmaf( C_, x[5], fmaf( B_, x[3], A_ * x[1])));
    float od1 = fmaf(-C_, x[7], fmaf(-A_, x[5], fmaf(-D_, x[3], B_ * x[1])));
    float od2 = fmaf( B_, x[7], fmaf( D_, x[5], fmaf(-A_, x[3], C_ * x[1])));
    float od3 = fmaf(-A_, x[7], fmaf( B_, x[5], fmaf(-C_, x[3], D_ * x[1])));
    o[0] = ev0 + od0; o[1] = ev1 + od1; o[2] = ev2 + od2; o[3] = ev3 + od3;
    o[4] = ev3 - od3; o[5] = ev2 - od2; o[6] = ev1 - od1; o[7] = ev0 - od0;
}

template <int S>
__device__ __forceinline__ void storerow(float* blk, int k, const float a[8]) {
    *reinterpret_cast<float4*>(blk + k * S)     = make_float4(a[0], a[1], a[2], a[3]);
    *reinterpret_cast<float4*>(blk + k * S + 4) = make_float4(a[4], a[5], a[6], a[7]);
}
template <int S>
__device__ __forceinline__ void loadrow(const float* blk, int k, float a[8]) {
    float4 v0 = *reinterpret_cast<const float4*>(blk + k * S);
    float4 v1 = *reinterpret_cast<const float4*>(blk + k * S + 4);
    a[0] = v0.x; a[1] = v0.y; a[2] = v0.z; a[3] = v0.w;
    a[4] = v1.x; a[5] = v1.y; a[6] = v1.z; a[7] = v1.w;
}
template <int S>
__device__ __forceinline__ void loadcol(const float* blk, int k, float a[8]) {
#pragma unroll
    for (int j = 0; j < 8; j++) a[j] = blk[j * S + k];
}

// Full DCT -> quant(RNE) -> dequant -> IDCT of one 8x8 block, done in-place in
// shared memory by an 8-thread group (thread k owns row k). Quant tables read
// from SMEM (broadcast, conflict-free) to keep register count low.
template <int S>
__device__ __forceinline__ void jpeg_block(float* blk, int k,
                                           const float* __restrict__ sq,
                                           const float* __restrict__ siq) {
    float x[8], a[8];
    loadrow<S>(blk, k, x);          // row k of X (same-thread row, no hazard)
    fdct8(x, a);                    // row k of A = X * D^T
    storerow<S>(blk, k, a);         // smem holds A
    __syncwarp();
    loadcol<S>(blk, k, x);          // row k of A^T
    fdct8(x, a);                    // row k of C^T   (C = D X D^T)
#pragma unroll
    for (int l = 0; l < 8; l++)     // quantize + dequantize (table transposed)
        a[l] = rne(a[l] * siq[l]) * sq[l];
    idct8(a, x);                    // row k of P^T   (P = D^T * deq)
    __syncwarp();
    storerow<S>(blk, k, x);         // smem holds P^T
    __syncwarp();
    loadcol<S>(blk, k, a);          // row k of P
    idct8(a, x);                    // row k of rec = D^T * deq * D
    __syncwarp();
    storerow<S>(blk, k, x);
}

__global__ void __launch_bounds__(256, 6)
jpeg_kernel(const float* __restrict__ in, float* __restrict__ out) {
    __shared__ float sY[TILE * SYS];
    __shared__ float sCb[32 * SCS];
    __shared__ float sCr[32 * SCS];
    __shared__ float sTab[256];

    const int tid = threadIdx.x;
    const int tx0 = blockIdx.x * TILE;
    const int ty0 = blockIdx.y * TILE;
    const int img = blockIdx.z;

    sTab[tid] = c_tab[tid];         // quant tables -> smem (covered by the
                                    // phase-1 __syncthreads below)

    const float* src = in  + (((size_t)img * IMGW + ty0) * IMGW + tx0) * 3;
    float*       dst = out + (((size_t)img * IMGW + ty0) * IMGW + tx0) * 3;

    // ---------- phase 1: load, x255, RGB->YCbCr (level shifted), 4:2:0 down ----
#pragma unroll
    for (int qq = 0; qq < 4; qq++) {
        int qid = tid + qq * 256;
        int qr = qid >> 5, qc = qid & 31;
        const float* p = src + (qr * 2) * (IMGW * 3) + qc * 6;
        float cbs = 0.0f, crs = 0.0f;
#pragma unroll
        for (int dy = 0; dy < 2; dy++) {
            const float* pr = p + dy * (IMGW * 3);
            float2 u0 = *reinterpret_cast<const float2*>(pr);
            float2 u1 = *reinterpret_cast<const float2*>(pr + 2);
            float2 u2 = *reinterpret_cast<const float2*>(pr + 4);
            float rv[2] = { u0.x, u1.y };
            float gv[2] = { u0.y, u2.x };
            float bv[2] = { u1.x, u2.y };
#pragma unroll
            for (int dx = 0; dx < 2; dx++) {
                // input is uniform [0,1): floor(x*255) in [0,254], no clip needed
                float r = floorf(rv[dx] * 255.0f);
                float g = floorf(gv[dx] * 255.0f);
                float b = floorf(bv[dx] * 255.0f);
                float yv = fmaf(r, 0.299f, fmaf(g, 0.587f, fmaf(b, 0.114f, -128.0f)));
                cbs += fmaf(r, -0.168736f, fmaf(g, -0.331264f, b * 0.5f));
                crs += fmaf(r, 0.5f, fmaf(g, -0.418688f, b * (-0.081312f)));
                sY[(qr * 2 + dy) * SYS + qc * 2 + dx] = yv;
            }
        }
        sCb[qr * SCS + qc] = cbs * 0.25f;
        sCr[qr * SCS + qc] = crs * 0.25f;
    }
    __syncthreads();

    // ---------- phase 2: 8x8 blocks. 32 groups x 3 blocks (2 luma + 1 chroma) --
    {
        const int grp = tid >> 3;
        const int k   = tid & 7;

        const float* sql  = sTab + k * 8;          // luma q row (transposed)
        const float* siql = sTab + 64 + k * 8;     // luma 1/q
        const float* sqc  = sTab + 128 + k * 8;    // chroma q
        const float* siqc = sTab + 192 + k * 8;    // chroma 1/q

        float* yb0 = sY + (grp >> 3) * (8 * SYS) + (grp & 7) * 8;
        jpeg_block<SYS>(yb0, k, sql, siql);
        float* yb1 = sY + ((grp >> 3) + 4) * (8 * SYS) + (grp & 7) * 8;
        jpeg_block<SYS>(yb1, k, sql, siql);

        int cg = grp & 15;
        float* cbase = (grp < 16) ? sCb : sCr;
        float* cb = cbase + (cg >> 2) * (8 * SCS) + (cg & 3) * 8;
        jpeg_block<SCS>(cb, k, sqc, siqc);
    }
    __syncthreads();

    // ---------- phase 3: upsample chroma, YCbCr->RGB, clip, round, /255 -------
#pragma unroll
    for (int qq = 0; qq < 4; qq++) {
        int qid = tid + qq * 256;
        int qr = qid >> 5, qc = qid & 31;
        float cbv = sCb[qr * SCS + qc];
        float crv = sCr[qr * SCS + qc];
        float* p = dst + (qr * 2) * (IMGW * 3) + qc * 6;
#pragma unroll
        for (int dy = 0; dy < 2; dy++) {
            float* pr = p + dy * (IMGW * 3);
            float vals[6];
#pragma unroll
            for (int dx = 0; dx < 2; dx++) {
                float y128 = sY[(qr * 2 + dy) * SYS + qc * 2 + dx] + 128.0f;
                float r2 = fmaf(crv, 1.402f, y128);
                float g2 = fmaf(cbv, -0.344136f, fmaf(crv, -0.714136f, y128));
                float b2 = fmaf(cbv, 1.772f, y128);
                r2 = rne(fminf(fmaxf(r2, 0.0f), 255.0f)) * (1.0f / 255.0f);
                g2 = rne(fminf(fmaxf(g2, 0.0f), 255.0f)) * (1.0f / 255.0f);
                b2 = rne(fminf(fmaxf(b2, 0.0f), 255.0f)) * (1.0f / 255.0f);
                vals[dx * 3 + 0] = r2; vals[dx * 3 + 1] = g2; vals[dx * 3 + 2] = b2;
            }
            *reinterpret_cast<float2*>(pr)     = make_float2(vals[0], vals[1]);
            *reinterpret_cast<float2*>(pr + 2) = make_float2(vals[2], vals[3]);
            *reinterpret_cast<float2*>(pr + 4) = make_float2(vals[4], vals[5]);
        }
    }
}

extern "C" void kernel_launch(void* const* d_in, const int* in_sizes, int n_in,
                              void* d_out, int out_size) {
    (void)in_sizes; (void)n_in; (void)out_size;
    dim3 grid(IMGW / TILE, IMGW / TILE, 32);
    jpeg_kernel<<<grid, 256>>>((const float*)d_in[0], (float*)d_out);
}

// round 3
// speedup vs baseline: 1.0856x; 1.0374x over previous
#include <cuda_runtime.h>

// ---------------- DCT-II 8-point constants (fp32, match np.float32(D)) ----
#define G_ 0.35355339059327373f
#define A_ 0.49039264020161522f
#define B_ 0.41573480615127262f
#define C_ 0.27778511650980114f
#define D_ 0.09754516100806417f
#define E_ 0.46193976625564337f
#define F_ 0.19134171618254492f

// Quant tables for QUALITY=95 in NATURAL layout, packed (q, 1/q).
// q = floor(base/10 + 0.5), clipped to [1,255].
#define QP(v) {(float)(v), 1.0f/(float)(v)}
__constant__ float2 c_tab2[128] = {
    // luma (natural row-major)
    QP(2),QP(1),QP(1),QP(2),QP(2),QP(4),QP(5),QP(6),
    QP(1),QP(1),QP(1),QP(2),QP(3),QP(6),QP(6),QP(6),
    QP(1),QP(1),QP(2),QP(2),QP(4),QP(6),QP(7),QP(6),
    QP(1),QP(2),QP(2),QP(3),QP(5),QP(9),QP(8),QP(6),
    QP(2),QP(2),QP(4),QP(6),QP(7),QP(11),QP(10),QP(8),
    QP(2),QP(4),QP(6),QP(6),QP(8),QP(10),QP(11),QP(9),
    QP(5),QP(6),QP(8),QP(9),QP(10),QP(12),QP(12),QP(10),
    QP(7),QP(9),QP(10),QP(10),QP(11),QP(10),QP(10),QP(10),
    // chroma (natural row-major, symmetric)
    QP(2),QP(2),QP(2),QP(5),QP(10),QP(10),QP(10),QP(10),
    QP(2),QP(2),QP(3),QP(7),QP(10),QP(10),QP(10),QP(10),
    QP(2),QP(3),QP(6),QP(10),QP(10),QP(10),QP(10),QP(10),
    QP(5),QP(7),QP(10),QP(10),QP(10),QP(10),QP(10),QP(10),
    QP(10),QP(10),QP(10),QP(10),QP(10),QP(10),QP(10),QP(10),
    QP(10),QP(10),QP(10),QP(10),QP(10),QP(10),QP(10),QP(10),
    QP(10),QP(10),QP(10),QP(10),QP(10),QP(10),QP(10),QP(10),
    QP(10),QP(10),QP(10),QP(10),QP(10),QP(10),QP(10),QP(10)
};

#define IMGW 512
#define TILE 64
#define SYS  68   // padded stride of Y plane in smem
#define SCS  36   // padded stride of chroma planes

// round-to-nearest-even via magic constant (|x| < 2^22 guaranteed here)
__device__ __forceinline__ float rne(float v) {
    float t = fmaf(v, 1.0f, 12582912.0f);   // 1.5 * 2^23
    return fmaf(t, 1.0f, -12582912.0f);
}

// o[l] = sum_j x[j] * D[l][j]   (forward DCT of an 8-vector), butterflied
__device__ __forceinline__ void fdct8(const float x[8], float o[8]) {
    float s07 = x[0] + x[7], s16 = x[1] + x[6], s25 = x[2] + x[5], s34 = x[3] + x[4];
    float d07 = x[0] - x[7], d16 = x[1] - x[6], d25 = x[2] - x[5], d34 = x[3] - x[4];
    float e0 = s07 + s34, e1 = s16 + s25, e2 = s07 - s34, e3 = s16 - s25;
    o[0] = G_ * (e0 + e1);
    o[4] = G_ * (e0 - e1);
    o[2] = fmaf( F_, e3, E_ * e2);
    o[6] = fmaf(-E_, e3, F_ * e2);
    o[1] = fmaf( D_, d34, fmaf( C_, d25, fmaf( B_, d16, A_ * d07)));
    o[3] = fmaf(-C_, d34, fmaf(-A_, d25, fmaf(-D_, d16, B_ * d07)));
    o[5] = fmaf( B_, d34, fmaf( D_, d25, fmaf(-A_, d16, C_ * d07)));
    o[7] = fmaf(-A_, d34, fmaf( B_, d25, fmaf(-C_, d16, D_ * d07)));
}

// o[j] = sum_l x[l] * D[l][j]   (inverse DCT of an 8-vector), butterflied
__device__ __forceinline__ void idct8(const float x[8], float o[8]) {
    float ee0 = G_ * (x[0] + x[4]);
    float ee1 = G_ * (x[0] - x[4]);
    float eo0 = fmaf( F_, x[6], E_ * x[2]);
    float eo1 = fmaf(-E_, x[6], F_ * x[2]);
    float ev0 = ee0 + eo0, ev1 = ee1 + eo1, ev2 = ee1 - eo1, ev3 = ee0 - eo0;
    float od0 = fmaf( D_, x[7], fmaf( C_, x[5], fmaf( B_, x[3], A_ * x[1])));
    float od1 = fmaf(-C_, x[7], fmaf(-A_, x[5], fmaf(-D_, x[3], B_ * x[1])));
    float od2 = fmaf( B_, x[7], fmaf( D_, x[5], fmaf(-A_, x[3], C_ * x[1])));
    float od3 = fmaf(-A_, x[7], fmaf( B_, x[5], fmaf(-C_, x[3], D_ * x[1])));
    o[0] = ev0 + od0; o[1] = ev1 + od1; o[2] = ev2 + od2; o[3] = ev3 + od3;
    o[4] = ev3 - od3; o[5] = ev2 - od2; o[6] = ev1 - od1; o[7] = ev0 - od0;
}

// Eklundh 8x8 transpose among the 8 lanes of a group (lane = k = tid&7).
// Thread k holds row k in v[]; after, thread k holds column k.
// 3 stages x 4 shfl_xor. XOR distances < 8 stay inside the 8-lane group.
__device__ __forceinline__ void transpose8(float v[8], int k) {
#pragma unroll
    for (int s = 1; s < 8; s <<= 1) {
        const bool up = (k & s) != 0;
#pragma unroll
        for (int j = 0; j < 8; j++) {
            if ((j & s) == 0) {
                const int jp = j | s;
                float send = up ? v[j] : v[jp];
                float recv = __shfl_xor_sync(0xFFFFFFFFu, send, s, 32);
                if (up) v[j] = recv; else v[jp] = recv;
            }
        }
    }
}

template <int S>
__device__ __forceinline__ void storerow(float* blk, int k, const float a[8]) {
    *reinterpret_cast<float4*>(blk + k * S)     = make_float4(a[0], a[1], a[2], a[3]);
    *reinterpret_cast<float4*>(blk + k * S + 4) = make_float4(a[4], a[5], a[6], a[7]);
}
template <int S>
__device__ __forceinline__ void loadrow(const float* blk, int k, float a[8]) {
    float4 v0 = *reinterpret_cast<const float4*>(blk + k * S);
    float4 v1 = *reinterpret_cast<const float4*>(blk + k * S + 4);
    a[0] = v0.x; a[1] = v0.y; a[2] = v0.z; a[3] = v0.w;
    a[4] = v1.x; a[5] = v1.y; a[6] = v1.z; a[7] = v1.w;
}

// Full DCT -> quant(RNE) -> dequant -> IDCT of one 8x8 block by an 8-thread
// group. All transposes in registers via shfl; smem touched only at entry/exit.
// No __syncwarp needed: shfl provides the intra-group ordering, and the block
// is group-exclusive between the phase __syncthreads barriers.
template <int S>
__device__ __forceinline__ void jpeg_block(float* blk, int k,
                                           const float2* __restrict__ tab) {
    float x[8], a[8];
    loadrow<S>(blk, k, x);          // row k of X
    fdct8(x, a);                    // row k of A = X * D^T
    transpose8(a, k);               // row k of A^T
    fdct8(a, x);                    // row k of C^T   (C = D X D^T)
#pragma unroll
    for (int l = 0; l < 8; l++) {   // elem l is C[l][k] -> divisor Q[l][k]
        float2 t = tab[l * 8 + k];  // (q, 1/q), conflict-free + broadcast
        x[l] = rne(x[l] * t.y) * t.x;
    }
    idct8(x, a);                    // row k of P^T   (P = D^T * deq)
    transpose8(a, k);               // row k of P
    idct8(a, x);                    // row k of rec = D^T * deq * D
    storerow<S>(blk, k, x);
}

__global__ void __launch_bounds__(256, 6)
jpeg_kernel(const float* __restrict__ in, float* __restrict__ out) {
    __shared__ float sY[TILE * SYS];
    __shared__ float sCb[32 * SCS];
    __shared__ float sCr[32 * SCS];
    __shared__ float2 sTab2[128];

    const int tid = threadIdx.x;
    const int tx0 = blockIdx.x * TILE;
    const int ty0 = blockIdx.y * TILE;
    const int img = blockIdx.z;

    if (tid < 128) sTab2[tid] = c_tab2[tid];  // covered by phase-1 barrier

    const float* src = in  + (((size_t)img * IMGW + ty0) * IMGW + tx0) * 3;
    float*       dst = out + (((size_t)img * IMGW + ty0) * IMGW + tx0) * 3;

    // ---------- phase 1: load, x255, RGB->YCbCr (level shifted), 4:2:0 down ----
#pragma unroll
    for (int qq = 0; qq < 4; qq++) {
        int qid = tid + qq * 256;
        int qr = qid >> 5, qc = qid & 31;
        const float* p = src + (qr * 2) * (IMGW * 3) + qc * 6;
        float cbs = 0.0f, crs = 0.0f;
#pragma unroll
        for (int dy = 0; dy < 2; dy++) {
            const float* pr = p + dy * (IMGW * 3);
            float2 u0 = *reinterpret_cast<const float2*>(pr);
            float2 u1 = *reinterpret_cast<const float2*>(pr + 2);
            float2 u2 = *reinterpret_cast<const float2*>(pr + 4);
            float rv[2] = { u0.x, u1.y };
            float gv[2] = { u0.y, u2.x };
            float bv[2] = { u1.x, u2.y };
#pragma unroll
            for (int dx = 0; dx < 2; dx++) {
                // input is uniform [0,1): floor(x*255) in [0,254], no clip needed
                float r = floorf(rv[dx] * 255.0f);
                float g = floorf(gv[dx] * 255.0f);
                float b = floorf(bv[dx] * 255.0f);
                float yv = fmaf(r, 0.299f, fmaf(g, 0.587f, fmaf(b, 0.114f, -128.0f)));
                cbs += fmaf(r, -0.168736f, fmaf(g, -0.331264f, b * 0.5f));
                crs += fmaf(r, 0.5f, fmaf(g, -0.418688f, b * (-0.081312f)));
                sY[(qr * 2 + dy) * SYS + qc * 2 + dx] = yv;
            }
        }
        sCb[qr * SCS + qc] = cbs * 0.25f;
        sCr[qr * SCS + qc] = crs * 0.25f;
    }
    __syncthreads();

    // ---------- phase 2: 8x8 blocks. 32 groups x 3 blocks (2 luma + 1 chroma) --
    {
        const int grp = tid >> 3;
        const int k   = tid & 7;

        const float2* tl = sTab2;        // luma (q, 1/q) natural layout
        const float2* tc = sTab2 + 64;   // chroma

        float* yb0 = sY + (grp >> 3) * (8 * SYS) + (grp & 7) * 8;
        jpeg_block<SYS>(yb0, k, tl);
        float* yb1 = sY + ((grp >> 3) + 4) * (8 * SYS) + (grp & 7) * 8;
        jpeg_block<SYS>(yb1, k, tl);

        int cg = grp & 15;
        float* cbase = (grp < 16) ? sCb : sCr;
        float* cb = cbase + (cg >> 2) * (8 * SCS) + (cg & 3) * 8;
        jpeg_block<SCS>(cb, k, tc);
    }
    __syncthreads();

    // ---------- phase 3: upsample chroma, YCbCr->RGB, clip, round, /255 -------
#pragma unroll
    for (int qq = 0; qq < 4; qq++) {
        int qid = tid + qq * 256;
        int qr = qid >> 5, qc = qid & 31;
        float cbv = sCb[qr * SCS + qc];
        float crv = sCr[qr * SCS + qc];
        float* p = dst + (qr * 2) * (IMGW * 3) + qc * 6;
#pragma unroll
        for (int dy = 0; dy < 2; dy++) {
            float* pr = p + dy * (IMGW * 3);
            float vals[6];
#pragma unroll
            for (int dx = 0; dx < 2; dx++) {
                float y128 = sY[(qr * 2 + dy) * SYS + qc * 2 + dx] + 128.0f;
                float r2 = fmaf(crv, 1.402f, y128);
                float g2 = fmaf(cbv, -0.344136f, fmaf(crv, -0.714136f, y128));
                float b2 = fmaf(cbv, 1.772f, y128);
                r2 = rne(fminf(fmaxf(r2, 0.0f), 255.0f)) * (1.0f / 255.0f);
                g2 = rne(fminf(fmaxf(g2, 0.0f), 255.0f)) * (1.0f / 255.0f);
                b2 = rne(fminf(fmaxf(b2, 0.0f), 255.0f)) * (1.0f / 255.0f);
                vals[dx * 3 + 0] = r2; vals[dx * 3 + 1] = g2; vals[dx * 3 + 2] = b2;
            }
            *reinterpret_cast<float2*>(pr)     = make_float2(vals[0], vals[1]);
            *reinterpret_cast<float2*>(pr + 2) = make_float2(vals[2], vals[3]);
            *reinterpret_cast<float2*>(pr + 4) = make_float2(vals[4], vals[5]);
        }
    }
}

extern "C" void kernel_launch(void* const* d_in, const int* in_sizes, int n_in,
                              void* d_out, int out_size) {
    (void)in_sizes; (void)n_in; (void)out_size;
    dim3 grid(IMGW / TILE, IMGW / TILE, 32);
    jpeg_kernel<<<grid, 256>>>((const float*)d_in[0], (float*)d_out);
}

// round 4
// speedup vs baseline: 1.1018x; 1.0149x over previous
#include <cuda_runtime.h>

// ---------------- DCT-II 8-point constants (fp32, match np.float32(D)) ----
#define G_ 0.35355339059327373f
#define A_ 0.49039264020161522f
#define B_ 0.41573480615127262f
#define C_ 0.27778511650980114f
#define D_ 0.09754516100806417f
#define E_ 0.46193976625564337f
#define F_ 0.19134171618254492f

// Quant tables for QUALITY=95 in NATURAL layout, packed (q, 1/q).
#define QP(v) {(float)(v), 1.0f/(float)(v)}
__constant__ float2 c_tab2[128] = {
    // luma (natural row-major)
    QP(2),QP(1),QP(1),QP(2),QP(2),QP(4),QP(5),QP(6),
    QP(1),QP(1),QP(1),QP(2),QP(3),QP(6),QP(6),QP(6),
    QP(1),QP(1),QP(2),QP(2),QP(4),QP(6),QP(7),QP(6),
    QP(1),QP(2),QP(2),QP(3),QP(5),QP(9),QP(8),QP(6),
    QP(2),QP(2),QP(4),QP(6),QP(7),QP(11),QP(10),QP(8),
    QP(2),QP(4),QP(6),QP(6),QP(8),QP(10),QP(11),QP(9),
    QP(5),QP(6),QP(8),QP(9),QP(10),QP(12),QP(12),QP(10),
    QP(7),QP(9),QP(10),QP(10),QP(11),QP(10),QP(10),QP(10),
    // chroma (natural row-major, symmetric)
    QP(2),QP(2),QP(2),QP(5),QP(10),QP(10),QP(10),QP(10),
    QP(2),QP(2),QP(3),QP(7),QP(10),QP(10),QP(10),QP(10),
    QP(2),QP(3),QP(6),QP(10),QP(10),QP(10),QP(10),QP(10),
    QP(5),QP(7),QP(10),QP(10),QP(10),QP(10),QP(10),QP(10),
    QP(10),QP(10),QP(10),QP(10),QP(10),QP(10),QP(10),QP(10),
    QP(10),QP(10),QP(10),QP(10),QP(10),QP(10),QP(10),QP(10),
    QP(10),QP(10),QP(10),QP(10),QP(10),QP(10),QP(10),QP(10),
    QP(10),QP(10),QP(10),QP(10),QP(10),QP(10),QP(10),QP(10)
};

#define IMGW 512
#define TILE 64
#define SYS  68   // padded stride of Y plane in smem
#define SCS  36   // padded stride of chroma planes

// round-to-nearest-even via magic constant (|x| < 2^22 guaranteed here)
__device__ __forceinline__ float rne(float v) {
    float t = fmaf(v, 1.0f, 12582912.0f);   // 1.5 * 2^23
    return fmaf(t, 1.0f, -12582912.0f);
}

__device__ __forceinline__ void fdct8(const float x[8], float o[8]) {
    float s07 = x[0] + x[7], s16 = x[1] + x[6], s25 = x[2] + x[5], s34 = x[3] + x[4];
    float d07 = x[0] - x[7], d16 = x[1] - x[6], d25 = x[2] - x[5], d34 = x[3] - x[4];
    float e0 = s07 + s34, e1 = s16 + s25, e2 = s07 - s34, e3 = s16 - s25;
    o[0] = G_ * (e0 + e1);
    o[4] = G_ * (e0 - e1);
    o[2] = fmaf( F_, e3, E_ * e2);
    o[6] = fmaf(-E_, e3, F_ * e2);
    o[1] = fmaf( D_, d34, fmaf( C_, d25, fmaf( B_, d16, A_ * d07)));
    o[3] = fmaf(-C_, d34, fmaf(-A_, d25, fmaf(-D_, d16, B_ * d07)));
    o[5] = fmaf( B_, d34, fmaf( D_, d25, fmaf(-A_, d16, C_ * d07)));
    o[7] = fmaf(-A_, d34, fmaf( B_, d25, fmaf(-C_, d16, D_ * d07)));
}

__device__ __forceinline__ void idct8(const float x[8], float o[8]) {
    float ee0 = G_ * (x[0] + x[4]);
    float ee1 = G_ * (x[0] - x[4]);
    float eo0 = fmaf( F_, x[6], E_ * x[2]);
    float eo1 = fmaf(-E_, x[6], F_ * x[2]);
    float ev0 = ee0 + eo0, ev1 = ee1 + eo1, ev2 = ee1 - eo1, ev3 = ee0 - eo0;
    float od0 = fmaf( D_, x[7], fmaf( C_, x[5], fmaf( B_, x[3], A_ * x[1])));
    float od1 = fmaf(-C_, x[7], fmaf(-A_, x[5], fmaf(-D_, x[3], B_ * x[1])));
    float od2 = fmaf( B_, x[7], fmaf( D_, x[5], fmaf(-A_, x[3], C_ * x[1])));
    float od3 = fmaf(-A_, x[7], fmaf( B_, x[5], fmaf(-C_, x[3], D_ * x[1])));
    o[0] = ev0 + od0; o[1] = ev1 + od1; o[2] = ev2 + od2; o[3] = ev3 + od3;
    o[4] = ev3 - od3; o[5] = ev2 - od2; o[6] = ev1 - od1; o[7] = ev0 - od0;
}

// Eklundh 8x8 transpose among 8 lanes (lane = k = tid&7), single block.
__device__ __forceinline__ void transpose8(float v[8], int k) {
#pragma unroll
    for (int s = 1; s < 8; s <<= 1) {
        const bool up = (k & s) != 0;
#pragma unroll
        for (int j = 0; j < 8; j++) {
            if ((j & s) == 0) {
                const int jp = j | s;
                float send = up ? v[j] : v[jp];
                float recv = __shfl_xor_sync(0xFFFFFFFFu, send, s, 32);
                if (up) v[j] = recv; else v[jp] = recv;
            }
        }
    }
}

// Same, two independent blocks interleaved: shfl latencies overlap.
__device__ __forceinline__ void transpose8x2(float v0[8], float v1[8], int k) {
#pragma unroll
    for (int s = 1; s < 8; s <<= 1) {
        const bool up = (k & s) != 0;
#pragma unroll
        for (int j = 0; j < 8; j++) {
            if ((j & s) == 0) {
                const int jp = j | s;
                float s0 = up ? v0[j] : v0[jp];
                float s1 = up ? v1[j] : v1[jp];
                float r0 = __shfl_xor_sync(0xFFFFFFFFu, s0, s, 32);
                float r1 = __shfl_xor_sync(0xFFFFFFFFu, s1, s, 32);
                if (up) { v0[j] = r0; v1[j] = r1; }
                else    { v0[jp] = r0; v1[jp] = r1; }
            }
        }
    }
}

template <int S>
__device__ __forceinline__ void storerow(float* blk, int k, const float a[8]) {
    *reinterpret_cast<float4*>(blk + k * S)     = make_float4(a[0], a[1], a[2], a[3]);
    *reinterpret_cast<float4*>(blk + k * S + 4) = make_float4(a[4], a[5], a[6], a[7]);
}
template <int S>
__device__ __forceinline__ void loadrow(const float* blk, int k, float a[8]) {
    float4 v0 = *reinterpret_cast<const float4*>(blk + k * S);
    float4 v1 = *reinterpret_cast<const float4*>(blk + k * S + 4);
    a[0] = v0.x; a[1] = v0.y; a[2] = v0.z; a[3] = v0.w;
    a[4] = v1.x; a[5] = v1.y; a[6] = v1.z; a[7] = v1.w;
}

// Single 8x8 block roundtrip (used for chroma).
template <int S>
__device__ __forceinline__ void jpeg_block(float* blk, int k,
                                           const float2* __restrict__ tab) {
    float x[8], a[8];
    loadrow<S>(blk, k, x);
    fdct8(x, a);
    transpose8(a, k);
    fdct8(a, x);
#pragma unroll
    for (int l = 0; l < 8; l++) {
        float2 t = tab[l * 8 + k];
        x[l] = rne(x[l] * t.y) * t.x;
    }
    idct8(x, a);
    transpose8(a, k);
    idct8(a, x);
    storerow<S>(blk, k, x);
}

// Two independent 8x8 blocks processed concurrently (luma pair): doubles ILP
// on the shfl/fma dependency chains, shares the quant-table LDS.
template <int S>
__device__ __forceinline__ void jpeg_block2(float* b0, float* b1, int k,
                                            const float2* __restrict__ tab) {
    float x0[8], x1[8], a0[8], a1[8];
    loadrow<S>(b0, k, x0);
    loadrow<S>(b1, k, x1);
    fdct8(x0, a0);
    fdct8(x1, a1);
    transpose8x2(a0, a1, k);
    fdct8(a0, x0);
    fdct8(a1, x1);
#pragma unroll
    for (int l = 0; l < 8; l++) {
        float2 t = tab[l * 8 + k];
        x0[l] = rne(x0[l] * t.y) * t.x;
        x1[l] = rne(x1[l] * t.y) * t.x;
    }
    idct8(x0, a0);
    idct8(x1, a1);
    transpose8x2(a0, a1, k);
    idct8(a0, x0);
    idct8(a1, x1);
    storerow<S>(b0, k, x0);
    storerow<S>(b1, k, x1);
}

__global__ void __launch_bounds__(256, 4)
jpeg_kernel(const float* __restrict__ in, float* __restrict__ out) {
    __shared__ float sY[TILE * SYS];
    __shared__ float sCb[32 * SCS];
    __shared__ float sCr[32 * SCS];
    __shared__ float2 sTab2[128];

    const int tid = threadIdx.x;
    const int tx0 = blockIdx.x * TILE;
    const int ty0 = blockIdx.y * TILE;
    const int img = blockIdx.z;

    if (tid < 128) sTab2[tid] = c_tab2[tid];  // covered by phase-1 barrier

    const float* src = in  + (((size_t)img * IMGW + ty0) * IMGW + tx0) * 3;
    float*       dst = out + (((size_t)img * IMGW + ty0) * IMGW + tx0) * 3;

    // ---------- phase 1: LDG.128 load, x255, RGB->YCbCr, 4:2:0 downsample -----
    // Thread-iteration owns a 4x2 pixel region (4 wide, 2 tall) = 6 float4.
#pragma unroll
    for (int it = 0; it < 2; it++) {
        int sid = tid + it * 256;          // 0..511
        int tc  = sid & 15;                // 4-px column group (0..15)
        int ts  = sid >> 4;                // 2-row strip      (0..31)
        const float* p = src + (ts * 2) * (IMGW * 3) + tc * 12;
        float cbs[2] = {0.0f, 0.0f}, crs[2] = {0.0f, 0.0f};
#pragma unroll
        for (int dy = 0; dy < 2; dy++) {
            const float* pr = p + dy * (IMGW * 3);
            float4 q0 = *reinterpret_cast<const float4*>(pr);
            float4 q1 = *reinterpret_cast<const float4*>(pr + 4);
            float4 q2 = *reinterpret_cast<const float4*>(pr + 8);
            float rv[4] = { q0.x, q0.w, q1.z, q2.y };
            float gv[4] = { q0.y, q1.x, q1.w, q2.z };
            float bv[4] = { q0.z, q1.y, q2.x, q2.w };
            float y4[4];
#pragma unroll
            for (int i = 0; i < 4; i++) {
                // input uniform [0,1): floor(x*255) in [0,254], no clip needed
                float r = floorf(rv[i] * 255.0f);
                float g = floorf(gv[i] * 255.0f);
                float b = floorf(bv[i] * 255.0f);
                y4[i] = fmaf(r, 0.299f, fmaf(g, 0.587f, fmaf(b, 0.114f, -128.0f)));
                cbs[i >> 1] += fmaf(r, -0.168736f, fmaf(g, -0.331264f, b * 0.5f));
                crs[i >> 1] += fmaf(r, 0.5f, fmaf(g, -0.418688f, b * (-0.081312f)));
            }
            *reinterpret_cast<float4*>(&sY[(ts * 2 + dy) * SYS + tc * 4]) =
                make_float4(y4[0], y4[1], y4[2], y4[3]);
        }
        *reinterpret_cast<float2*>(&sCb[ts * SCS + tc * 2]) =
            make_float2(cbs[0] * 0.25f, cbs[1] * 0.25f);
        *reinterpret_cast<float2*>(&sCr[ts * SCS + tc * 2]) =
            make_float2(crs[0] * 0.25f, crs[1] * 0.25f);
    }
    __syncthreads();

    // ---------- phase 2: 32 groups x (1 interleaved luma pair + 1 chroma) -----
    {
        const int grp = tid >> 3;
        const int k   = tid & 7;

        const float2* tl = sTab2;        // luma (q, 1/q) natural layout
        const float2* tc2 = sTab2 + 64;  // chroma

        float* yb0 = sY + (grp >> 3) * (8 * SYS) + (grp & 7) * 8;
        float* yb1 = sY + ((grp >> 3) + 4) * (8 * SYS) + (grp & 7) * 8;
        jpeg_block2<SYS>(yb0, yb1, k, tl);

        int cg = grp & 15;
        float* cbase = (grp < 16) ? sCb : sCr;
        float* cb = cbase + (cg >> 2) * (8 * SCS) + (cg & 3) * 8;
        jpeg_block<SCS>(cb, k, tc2);
    }
    __syncthreads();

    // ---------- phase 3: upsample chroma, YCbCr->RGB, clip, round, STG.128 ----
#pragma unroll
    for (int it = 0; it < 2; it++) {
        int sid = tid + it * 256;
        int tc  = sid & 15;
        int ts  = sid >> 4;
        float2 cb2 = *reinterpret_cast<const float2*>(&sCb[ts * SCS + tc * 2]);
        float2 cr2 = *reinterpret_cast<const float2*>(&sCr[ts * SCS + tc * 2]);
        float cbv[4] = { cb2.x, cb2.x, cb2.y, cb2.y };
        float crv[4] = { cr2.x, cr2.x, cr2.y, cr2.y };
        float* p = dst + (ts * 2) * (IMGW * 3) + tc * 12;
#pragma unroll
        for (int dy = 0; dy < 2; dy++) {
            float4 y4 = *reinterpret_cast<const float4*>(&sY[(ts * 2 + dy) * SYS + tc * 4]);
            float yv[4] = { y4.x, y4.y, y4.z, y4.w };
            float o[12];
#pragma unroll
            for (int i = 0; i < 4; i++) {
                float y128 = yv[i] + 128.0f;
                float r2 = fmaf(crv[i], 1.402f, y128);
                float g2 = fmaf(cbv[i], -0.344136f, fmaf(crv[i], -0.714136f, y128));
                float b2 = fmaf(cbv[i], 1.772f, y128);
                o[i*3+0] = rne(fminf(fmaxf(r2, 0.0f), 255.0f)) * (1.0f / 255.0f);
                o[i*3+1] = rne(fminf(fmaxf(g2, 0.0f), 255.0f)) * (1.0f / 255.0f);
                o[i*3+2] = rne(fminf(fmaxf(b2, 0.0f), 255.0f)) * (1.0f / 255.0f);
            }
            float* pr = p + dy * (IMGW * 3);
            *reinterpret_cast<float4*>(pr)     = make_float4(o[0], o[1], o[2], o[3]);
            *reinterpret_cast<float4*>(pr + 4) = make_float4(o[4], o[5], o[6], o[7]);
            *reinterpret_cast<float4*>(pr + 8) = make_float4(o[8], o[9], o[10], o[11]);
        }
    }
}

extern "C" void kernel_launch(void* const* d_in, const int* in_sizes, int n_in,
                              void* d_out, int out_size) {
    (void)in_sizes; (void)n_in; (void)out_size;
    dim3 grid(IMGW / TILE, IMGW / TILE, 32);
    jpeg_kernel<<<grid, 256>>>((const float*)d_in[0], (float*)d_out);
}

// round 5
// speedup vs baseline: 1.1485x; 1.0424x over previous
#include <cuda_runtime.h>

// ---------------- DCT-II 8-point constants (fp32, match np.float32(D)) ----
#define G_ 0.35355339059327373f
#define A_ 0.49039264020161522f
#define B_ 0.41573480615127262f
#define C_ 0.27778511650980114f
#define D_ 0.09754516100806417f
#define E_ 0.46193976625564337f
#define F_ 0.19134171618254492f

// Quant tables for QUALITY=95 in NATURAL layout, packed (q, 1/q).
#define QP(v) {(float)(v), 1.0f/(float)(v)}
__constant__ float2 c_tab2[128] = {
    // luma (natural row-major)
    QP(2),QP(1),QP(1),QP(2),QP(2),QP(4),QP(5),QP(6),
    QP(1),QP(1),QP(1),QP(2),QP(3),QP(6),QP(6),QP(6),
    QP(1),QP(1),QP(2),QP(2),QP(4),QP(6),QP(7),QP(6),
    QP(1),QP(2),QP(2),QP(3),QP(5),QP(9),QP(8),QP(6),
    QP(2),QP(2),QP(4),QP(6),QP(7),QP(11),QP(10),QP(8),
    QP(2),QP(4),QP(6),QP(6),QP(8),QP(10),QP(11),QP(9),
    QP(5),QP(6),QP(8),QP(9),QP(10),QP(12),QP(12),QP(10),
    QP(7),QP(9),QP(10),QP(10),QP(11),QP(10),QP(10),QP(10),
    // chroma (natural row-major, symmetric)
    QP(2),QP(2),QP(2),QP(5),QP(10),QP(10),QP(10),QP(10),
    QP(2),QP(2),QP(3),QP(7),QP(10),QP(10),QP(10),QP(10),
    QP(2),QP(3),QP(6),QP(10),QP(10),QP(10),QP(10),QP(10),
    QP(5),QP(7),QP(10),QP(10),QP(10),QP(10),QP(10),QP(10),
    QP(10),QP(10),QP(10),QP(10),QP(10),QP(10),QP(10),QP(10),
    QP(10),QP(10),QP(10),QP(10),QP(10),QP(10),QP(10),QP(10),
    QP(10),QP(10),QP(10),QP(10),QP(10),QP(10),QP(10),QP(10),
    QP(10),QP(10),QP(10),QP(10),QP(10),QP(10),QP(10),QP(10)
};

#define IMGW 512
#define TILE 64
#define SYS  68   // padded stride of Y plane in smem
#define SCS  36   // padded stride of chroma planes

// round-to-nearest-even via magic constant (|x| < 2^22 guaranteed here)
__device__ __forceinline__ float rne(float v) {
    float t = fmaf(v, 1.0f, 12582912.0f);   // 1.5 * 2^23
    return fmaf(t, 1.0f, -12582912.0f);
}

__device__ __forceinline__ void fdct8(const float x[8], float o[8]) {
    float s07 = x[0] + x[7], s16 = x[1] + x[6], s25 = x[2] + x[5], s34 = x[3] + x[4];
    float d07 = x[0] - x[7], d16 = x[1] - x[6], d25 = x[2] - x[5], d34 = x[3] - x[4];
    float e0 = s07 + s34, e1 = s16 + s25, e2 = s07 - s34, e3 = s16 - s25;
    o[0] = G_ * (e0 + e1);
    o[4] = G_ * (e0 - e1);
    o[2] = fmaf( F_, e3, E_ * e2);
    o[6] = fmaf(-E_, e3, F_ * e2);
    o[1] = fmaf( D_, d34, fmaf( C_, d25, fmaf( B_, d16, A_ * d07)));
    o[3] = fmaf(-C_, d34, fmaf(-A_, d25, fmaf(-D_, d16, B_ * d07)));
    o[5] = fmaf( B_, d34, fmaf( D_, d25, fmaf(-A_, d16, C_ * d07)));
    o[7] = fmaf(-A_, d34, fmaf( B_, d25, fmaf(-C_, d16, D_ * d07)));
}

__device__ __forceinline__ void idct8(const float x[8], float o[8]) {
    float ee0 = G_ * (x[0] + x[4]);
    float ee1 = G_ * (x[0] - x[4]);
    float eo0 = fmaf( F_, x[6], E_ * x[2]);
    float eo1 = fmaf(-E_, x[6], F_ * x[2]);
    float ev0 = ee0 + eo0, ev1 = ee1 + eo1, ev2 = ee1 - eo1, ev3 = ee0 - eo0;
    float od0 = fmaf( D_, x[7], fmaf( C_, x[5], fmaf( B_, x[3], A_ * x[1])));
    float od1 = fmaf(-C_, x[7], fmaf(-A_, x[5], fmaf(-D_, x[3], B_ * x[1])));
    float od2 = fmaf( B_, x[7], fmaf( D_, x[5], fmaf(-A_, x[3], C_ * x[1])));
    float od3 = fmaf(-A_, x[7], fmaf( B_, x[5], fmaf(-C_, x[3], D_ * x[1])));
    o[0] = ev0 + od0; o[1] = ev1 + od1; o[2] = ev2 + od2; o[3] = ev3 + od3;
    o[4] = ev3 - od3; o[5] = ev2 - od2; o[6] = ev1 - od1; o[7] = ev0 - od0;
}

// Eklundh 8x8 transpose among 8 lanes (lane = k = tid&7), THREE independent
// blocks interleaved so the shfl latency chains overlap.
__device__ __forceinline__ void transpose8x3(float v0[8], float v1[8], float v2[8],
                                             int k) {
#pragma unroll
    for (int s = 1; s < 8; s <<= 1) {
        const bool up = (k & s) != 0;
#pragma unroll
        for (int j = 0; j < 8; j++) {
            if ((j & s) == 0) {
                const int jp = j | s;
                float s0 = up ? v0[j] : v0[jp];
                float s1 = up ? v1[j] : v1[jp];
                float s2 = up ? v2[j] : v2[jp];
                float r0 = __shfl_xor_sync(0xFFFFFFFFu, s0, s, 32);
                float r1 = __shfl_xor_sync(0xFFFFFFFFu, s1, s, 32);
                float r2 = __shfl_xor_sync(0xFFFFFFFFu, s2, s, 32);
                if (up) { v0[j] = r0; v1[j] = r1; v2[j] = r2; }
                else    { v0[jp] = r0; v1[jp] = r1; v2[jp] = r2; }
            }
        }
    }
}

template <int S>
__device__ __forceinline__ void storerow(float* blk, int k, const float a[8]) {
    *reinterpret_cast<float4*>(blk + k * S)     = make_float4(a[0], a[1], a[2], a[3]);
    *reinterpret_cast<float4*>(blk + k * S + 4) = make_float4(a[4], a[5], a[6], a[7]);
}
template <int S>
__device__ __forceinline__ void loadrow(const float* blk, int k, float a[8]) {
    float4 v0 = *reinterpret_cast<const float4*>(blk + k * S);
    float4 v1 = *reinterpret_cast<const float4*>(blk + k * S + 4);
    a[0] = v0.x; a[1] = v0.y; a[2] = v0.z; a[3] = v0.w;
    a[4] = v1.x; a[5] = v1.y; a[6] = v1.z; a[7] = v1.w;
}

// THREE independent 8x8 blocks (2 luma + 1 chroma) processed concurrently by
// one 8-thread group: triples ILP on the shfl/fma dependency chains.
template <int SL, int SC>
__device__ __forceinline__ void jpeg_block3(float* b0, float* b1, float* b2, int k,
                                            const float2* __restrict__ tabL,
                                            const float2* __restrict__ tabC) {
    float x0[8], x1[8], x2[8], a0[8], a1[8], a2[8];
    loadrow<SL>(b0, k, x0);
    loadrow<SL>(b1, k, x1);
    loadrow<SC>(b2, k, x2);
    fdct8(x0, a0);
    fdct8(x1, a1);
    fdct8(x2, a2);
    transpose8x3(a0, a1, a2, k);
    fdct8(a0, x0);
    fdct8(a1, x1);
    fdct8(a2, x2);
#pragma unroll
    for (int l = 0; l < 8; l++) {
        float2 t = tabL[l * 8 + k];   // shared by both luma blocks
        float2 u = tabC[l * 8 + k];
        x0[l] = rne(x0[l] * t.y) * t.x;
        x1[l] = rne(x1[l] * t.y) * t.x;
        x2[l] = rne(x2[l] * u.y) * u.x;
    }
    idct8(x0, a0);
    idct8(x1, a1);
    idct8(x2, a2);
    transpose8x3(a0, a1, a2, k);
    idct8(a0, x0);
    idct8(a1, x1);
    idct8(a2, x2);
    storerow<SL>(b0, k, x0);
    storerow<SL>(b1, k, x1);
    storerow<SC>(b2, k, x2);
}

__global__ void __launch_bounds__(256, 3)
jpeg_kernel(const float* __restrict__ in, float* __restrict__ out) {
    __shared__ float sY[TILE * SYS];
    __shared__ float sCb[32 * SCS];
    __shared__ float sCr[32 * SCS];
    __shared__ float2 sTab2[128];

    const int tid = threadIdx.x;
    const int tx0 = blockIdx.x * TILE;
    const int ty0 = blockIdx.y * TILE;
    const int img = blockIdx.z;

    if (tid < 128) sTab2[tid] = c_tab2[tid];  // covered by phase-1 barrier

    const float* src = in  + (((size_t)img * IMGW + ty0) * IMGW + tx0) * 3;
    float*       dst = out + (((size_t)img * IMGW + ty0) * IMGW + tx0) * 3;

    // ---------- phase 1: LDG.128 load, x255, RGB->YCbCr, 4:2:0 downsample -----
#pragma unroll
    for (int it = 0; it < 2; it++) {
        int sid = tid + it * 256;          // 0..511
        int tc  = sid & 15;                // 4-px column group (0..15)
        int ts  = sid >> 4;                // 2-row strip      (0..31)
        const float* p = src + (ts * 2) * (IMGW * 3) + tc * 12;
        float cbs[2] = {0.0f, 0.0f}, crs[2] = {0.0f, 0.0f};
#pragma unroll
        for (int dy = 0; dy < 2; dy++) {
            const float* pr = p + dy * (IMGW * 3);
            float4 q0 = *reinterpret_cast<const float4*>(pr);
            float4 q1 = *reinterpret_cast<const float4*>(pr + 4);
            float4 q2 = *reinterpret_cast<const float4*>(pr + 8);
            float rv[4] = { q0.x, q0.w, q1.z, q2.y };
            float gv[4] = { q0.y, q1.x, q1.w, q2.z };
            float bv[4] = { q0.z, q1.y, q2.x, q2.w };
            float y4[4];
#pragma unroll
            for (int i = 0; i < 4; i++) {
                // input uniform [0,1): floor(x*255) in [0,254], no clip needed
                float r = floorf(rv[i] * 255.0f);
                float g = floorf(gv[i] * 255.0f);
                float b = floorf(bv[i] * 255.0f);
                y4[i] = fmaf(r, 0.299f, fmaf(g, 0.587f, fmaf(b, 0.114f, -128.0f)));
                cbs[i >> 1] += fmaf(r, -0.168736f, fmaf(g, -0.331264f, b * 0.5f));
                crs[i >> 1] += fmaf(r, 0.5f, fmaf(g, -0.418688f, b * (-0.081312f)));
            }
            *reinterpret_cast<float4*>(&sY[(ts * 2 + dy) * SYS + tc * 4]) =
                make_float4(y4[0], y4[1], y4[2], y4[3]);
        }
        *reinterpret_cast<float2*>(&sCb[ts * SCS + tc * 2]) =
            make_float2(cbs[0] * 0.25f, cbs[1] * 0.25f);
        *reinterpret_cast<float2*>(&sCr[ts * SCS + tc * 2]) =
            make_float2(crs[0] * 0.25f, crs[1] * 0.25f);
    }
    __syncthreads();

    // ---------- phase 2: 32 groups x 3 blocks, all interleaved ----------------
    {
        const int grp = tid >> 3;
        const int k   = tid & 7;

        const float2* tl = sTab2;        // luma (q, 1/q) natural layout
        const float2* tc2 = sTab2 + 64;  // chroma

        float* yb0 = sY + (grp >> 3) * (8 * SYS) + (grp & 7) * 8;
        float* yb1 = sY + ((grp >> 3) + 4) * (8 * SYS) + (grp & 7) * 8;

        int cg = grp & 15;
        float* cbase = (grp < 16) ? sCb : sCr;
        float* cb = cbase + (cg >> 2) * (8 * SCS) + (cg & 3) * 8;

        jpeg_block3<SYS, SCS>(yb0, yb1, cb, k, tl, tc2);
    }
    __syncthreads();

    // ---------- phase 3: upsample chroma, YCbCr->RGB, clip, round, STG.128 ----
#pragma unroll
    for (int it = 0; it < 2; it++) {
        int sid = tid + it * 256;
        int tc  = sid & 15;
        int ts  = sid >> 4;
        float2 cb2 = *reinterpret_cast<const float2*>(&sCb[ts * SCS + tc * 2]);
        float2 cr2 = *reinterpret_cast<const float2*>(&sCr[ts * SCS + tc * 2]);
        float cbv[4] = { cb2.x, cb2.x, cb2.y, cb2.y };
        float crv[4] = { cr2.x, cr2.x, cr2.y, cr2.y };
        float* p = dst + (ts * 2) * (IMGW * 3) + tc * 12;
#pragma unroll
        for (int dy = 0; dy < 2; dy++) {
            float4 y4 = *reinterpret_cast<const float4*>(&sY[(ts * 2 + dy) * SYS + tc * 4]);
            float yv[4] = { y4.x, y4.y, y4.z, y4.w };
            float o[12];
#pragma unroll
            for (int i = 0; i < 4; i++) {
                float y128 = yv[i] + 128.0f;
                float r2 = fmaf(crv[i], 1.402f, y128);
                float g2 = fmaf(cbv[i], -0.344136f, fmaf(crv[i], -0.714136f, y128));
                float b2 = fmaf(cbv[i], 1.772f, y128);
                o[i*3+0] = rne(fminf(fmaxf(r2, 0.0f), 255.0f)) * (1.0f / 255.0f);
                o[i*3+1] = rne(fminf(fmaxf(g2, 0.0f), 255.0f)) * (1.0f / 255.0f);
                o[i*3+2] = rne(fminf(fmaxf(b2, 0.0f), 255.0f)) * (1.0f / 255.0f);
            }
            float* pr = p + dy * (IMGW * 3);
            *reinterpret_cast<float4*>(pr)     = make_float4(o[0], o[1], o[2], o[3]);
            *reinterpret_cast<float4*>(pr + 4) = make_float4(o[4], o[5], o[6], o[7]);
            *reinterpret_cast<float4*>(pr + 8) = make_float4(o[8], o[9], o[10], o[11]);
        }
    }
}

extern "C" void kernel_launch(void* const* d_in, const int* in_sizes, int n_in,
                              void* d_out, int out_size) {
    (void)in_sizes; (void)n_in; (void)out_size;
    dim3 grid(IMGW / TILE, IMGW / TILE, 32);
    jpeg_kernel<<<grid, 256>>>((const float*)d_in[0], (float*)d_out);
}